// round 1
// baseline (speedup 1.0000x reference)
#include <cuda_runtime.h>
#include <math.h>

// Problem constants
#define Dm 512
#define Tt 2048
#define Bb 4
#define BT 8192          // Bb*Tt
#define FFd 2048
#define Ee 4
#define MAXTOK 8192
#define NCHUNK 16

// ---------------- scratch (device globals: allocation-free) ----------------
__device__ float g_K[BT * Dm];
__device__ float g_V[BT * Dm];
__device__ float g_wv[BT * Dm];
__device__ float g_tmp[BT * Dm];
__device__ float g_x1[BT * Dm];
__device__ float g_part[Bb * NCHUNK * Dm];
__device__ float g_kvsum[Bb * Dm];
__device__ int   g_counts[Ee];
__device__ int   g_tok[Ee * MAXTOK];
__device__ float g_wslot[Ee * MAXTOK];
__device__ int   g_slottok[BT * 2];
__device__ float g_h[(size_t)Ee * MAXTOK * FFd];     // 256 MB
__device__ float g_ybuf[(size_t)Ee * MAXTOK * Dm];   // 64 MB

// ---------------- misc small kernels ----------------
__global__ void zero_counts_kernel() {
    if (threadIdx.x < Ee) g_counts[threadIdx.x] = 0;
}

// kv_sum partials: grid(NCHUNK, Bb), block 512
__global__ void kvsum_partial_kernel() {
    int b = blockIdx.y, tc = blockIdx.x, d = threadIdx.x;
    const float* Kp = g_K + ((long long)b * Tt + (long long)tc * (Tt / NCHUNK)) * Dm;
    const float* Vp = g_V + ((long long)b * Tt + (long long)tc * (Tt / NCHUNK)) * Dm;
    float s = 0.f;
    for (int t = 0; t < Tt / NCHUNK; ++t)
        s += Kp[(long long)t * Dm + d] * Vp[(long long)t * Dm + d];
    g_part[((long long)b * NCHUNK + tc) * Dm + d] = s;
}

// reduce partials: grid 8, block 256  (Bb*Dm = 2048 outputs)
__global__ void kvsum_reduce_kernel() {
    int i = blockIdx.x * 256 + threadIdx.x;  // i = b*Dm + d
    int b = i >> 9, d = i & 511;
    float s = 0.f;
    for (int tc = 0; tc < NCHUNK; ++tc)
        s += g_part[((long long)b * NCHUNK + tc) * Dm + d];
    g_kvsum[i] = s;
}

// ---------------- generic tiled GEMM: C[z] = A[z] @ B[z] + bias[z] ----------------
// BM=BN=128, BK=8, 256 threads, 8x8 microtile. Requires M%128==0, N%128==0, K%8==0.
__global__ __launch_bounds__(256) void gemm_bias_kernel(
    const float* __restrict__ A, const float* __restrict__ Bm,
    const float* __restrict__ bias, float* __restrict__ C,
    int M, int N, int K,
    long long sA, long long sB, long long sC, long long sBias)
{
    int z = blockIdx.z;
    A  += (long long)z * sA;
    Bm += (long long)z * sB;
    C  += (long long)z * sC;
    const float* bz = bias + (long long)z * sBias;

    __shared__ float As[8][128];
    __shared__ float Bs[8][132];

    int tid = threadIdx.x;
    int tx = tid & 15, ty = tid >> 4;
    int row0 = blockIdx.y * 128, col0 = blockIdx.x * 128;
    int aRow = tid >> 1, aK4 = (tid & 1) * 4;
    int bK = tid >> 5, bN4 = (tid & 31) * 4;

    const float* Aptr = A + (long long)(row0 + aRow) * K + aK4;
    const float* Bptr = Bm + (long long)bK * N + col0 + bN4;

    float acc[8][8];
#pragma unroll
    for (int i = 0; i < 8; i++)
#pragma unroll
        for (int j = 0; j < 8; j++) acc[i][j] = 0.f;

    for (int k0 = 0; k0 < K; k0 += 8) {
        float4 a4 = *reinterpret_cast<const float4*>(Aptr + k0);
        float4 b4 = *reinterpret_cast<const float4*>(Bptr + (long long)k0 * N);
        As[aK4 + 0][aRow] = a4.x; As[aK4 + 1][aRow] = a4.y;
        As[aK4 + 2][aRow] = a4.z; As[aK4 + 3][aRow] = a4.w;
        *reinterpret_cast<float4*>(&Bs[bK][bN4]) = b4;
        __syncthreads();
#pragma unroll
        for (int k = 0; k < 8; k++) {
            float4 a0 = *reinterpret_cast<const float4*>(&As[k][ty * 8]);
            float4 a1 = *reinterpret_cast<const float4*>(&As[k][ty * 8 + 4]);
            float4 b0 = *reinterpret_cast<const float4*>(&Bs[k][tx * 8]);
            float4 b1 = *reinterpret_cast<const float4*>(&Bs[k][tx * 8 + 4]);
            float ra[8] = {a0.x, a0.y, a0.z, a0.w, a1.x, a1.y, a1.z, a1.w};
            float rb[8] = {b0.x, b0.y, b0.z, b0.w, b1.x, b1.y, b1.z, b1.w};
#pragma unroll
            for (int i = 0; i < 8; i++)
#pragma unroll
                for (int j = 0; j < 8; j++)
                    acc[i][j] = fmaf(ra[i], rb[j], acc[i][j]);
        }
        __syncthreads();
    }
#pragma unroll
    for (int i = 0; i < 8; i++) {
        long long r = row0 + ty * 8 + i;
#pragma unroll
        for (int j = 0; j < 8; j++) {
            int c = col0 + tx * 8 + j;
            C[r * N + c] = acc[i][j] + bz[c];
        }
    }
}

// ---------------- LN1: x1 = LN(x + tmp) ----------------
__global__ __launch_bounds__(256) void add_ln1_kernel(
    const float* __restrict__ x, const float* __restrict__ g, const float* __restrict__ b)
{
    int t = blockIdx.x, tid = threadIdx.x;
    const float* xr = x + (long long)t * Dm;
    const float* tr = g_tmp + (long long)t * Dm;
    float v0 = xr[tid] + tr[tid];
    float v1 = xr[tid + 256] + tr[tid + 256];
    __shared__ float red[256];
    red[tid] = v0 + v1;
    __syncthreads();
    for (int off = 128; off; off >>= 1) { if (tid < off) red[tid] += red[tid + off]; __syncthreads(); }
    float mu = red[0] * (1.0f / 512.0f);
    __syncthreads();
    float d0 = v0 - mu, d1 = v1 - mu;
    red[tid] = d0 * d0 + d1 * d1;
    __syncthreads();
    for (int off = 128; off; off >>= 1) { if (tid < off) red[tid] += red[tid + off]; __syncthreads(); }
    float inv = rsqrtf(red[0] * (1.0f / 512.0f) + 1e-5f);
    g_x1[(long long)t * Dm + tid]       = d0 * inv * g[tid] + b[tid];
    g_x1[(long long)t * Dm + tid + 256] = d1 * inv * g[tid + 256] + b[tid + 256];
}

// ---------------- gate: softmax(x1@Wg+bg), top-2, build expert slot lists ----------------
__global__ __launch_bounds__(128) void gate_kernel(
    const float* __restrict__ Wg, const float* __restrict__ bg)
{
    int t = blockIdx.x, tid = threadIdx.x;
    const float* xr = g_x1 + (long long)t * Dm;
    float p0 = 0, p1 = 0, p2 = 0, p3 = 0;
    const float4* Wg4 = reinterpret_cast<const float4*>(Wg);
    for (int d = tid; d < Dm; d += 128) {
        float xv = xr[d];
        float4 w = Wg4[d];
        p0 = fmaf(xv, w.x, p0); p1 = fmaf(xv, w.y, p1);
        p2 = fmaf(xv, w.z, p2); p3 = fmaf(xv, w.w, p3);
    }
    __shared__ float sm[4][128];
    sm[0][tid] = p0; sm[1][tid] = p1; sm[2][tid] = p2; sm[3][tid] = p3;
    __syncthreads();
    for (int off = 64; off; off >>= 1) {
        if (tid < off) {
            sm[0][tid] += sm[0][tid + off];
            sm[1][tid] += sm[1][tid + off];
            sm[2][tid] += sm[2][tid + off];
            sm[3][tid] += sm[3][tid + off];
        }
        __syncthreads();
    }
    if (tid == 0) {
        float s[4] = { sm[0][0] + bg[0], sm[1][0] + bg[1], sm[2][0] + bg[2], sm[3][0] + bg[3] };
        float m = fmaxf(fmaxf(s[0], s[1]), fmaxf(s[2], s[3]));
        float ex[4]; float sum = 0.f;
        for (int e = 0; e < 4; e++) { ex[e] = expf(s[e] - m); sum += ex[e]; }
        float invs = 1.0f / sum;
        float pr[4];
        for (int e = 0; e < 4; e++) pr[e] = ex[e] * invs;
        int i0 = 0;
        for (int e = 1; e < 4; e++) if (pr[e] > pr[i0]) i0 = e;
        int i1 = -1;
        for (int e = 0; e < 4; e++) {
            if (e == i0) continue;
            if (i1 < 0 || pr[e] > pr[i1]) i1 = e;
        }
        int s0 = atomicAdd(&g_counts[i0], 1);
        g_tok[i0 * MAXTOK + s0] = t;
        g_wslot[i0 * MAXTOK + s0] = pr[i0];
        g_slottok[2 * t] = i0 * MAXTOK + s0;
        int s1 = atomicAdd(&g_counts[i1], 1);
        g_tok[i1 * MAXTOK + s1] = t;
        g_wslot[i1 * MAXTOK + s1] = pr[i1];
        g_slottok[2 * t + 1] = i1 * MAXTOK + s1;
    }
}

// ---------------- MoE GEMM1 (gather): h = relu(x1[tok] @ W1[e] + b1[e]) ----------------
__global__ __launch_bounds__(256) void moe_gemm1_kernel(
    const float* __restrict__ W1, const float* __restrict__ b1)
{
    int e = blockIdx.z;
    int cnt = g_counts[e];
    int row0 = blockIdx.y * 128;
    if (row0 >= cnt) return;
    int col0 = blockIdx.x * 128;
    const float* Bm = W1 + (long long)e * Dm * FFd;   // [512, 2048]
    const float* bz = b1 + (long long)e * FFd;
    float* Ch = g_h + (long long)e * MAXTOK * FFd;

    __shared__ int toks[128];
    __shared__ float As[8][128];
    __shared__ float Bs[8][132];

    int tid = threadIdx.x;
    if (tid < 128) {
        int slot = row0 + tid;
        toks[tid] = (slot < cnt) ? g_tok[e * MAXTOK + slot] : 0;
    }
    __syncthreads();
    int tx = tid & 15, ty = tid >> 4;
    int aRow = tid >> 1, aK4 = (tid & 1) * 4;
    int bK = tid >> 5, bN4 = (tid & 31) * 4;
    const float* Aptr = g_x1 + (long long)toks[aRow] * Dm + aK4;
    const float* Bptr = Bm + (long long)bK * FFd + col0 + bN4;

    float acc[8][8];
#pragma unroll
    for (int i = 0; i < 8; i++)
#pragma unroll
        for (int j = 0; j < 8; j++) acc[i][j] = 0.f;

    for (int k0 = 0; k0 < Dm; k0 += 8) {
        float4 a4 = *reinterpret_cast<const float4*>(Aptr + k0);
        float4 b4 = *reinterpret_cast<const float4*>(Bptr + (long long)k0 * FFd);
        As[aK4 + 0][aRow] = a4.x; As[aK4 + 1][aRow] = a4.y;
        As[aK4 + 2][aRow] = a4.z; As[aK4 + 3][aRow] = a4.w;
        *reinterpret_cast<float4*>(&Bs[bK][bN4]) = b4;
        __syncthreads();
#pragma unroll
        for (int k = 0; k < 8; k++) {
            float4 a0 = *reinterpret_cast<const float4*>(&As[k][ty * 8]);
            float4 a1 = *reinterpret_cast<const float4*>(&As[k][ty * 8 + 4]);
            float4 b0 = *reinterpret_cast<const float4*>(&Bs[k][tx * 8]);
            float4 b1v = *reinterpret_cast<const float4*>(&Bs[k][tx * 8 + 4]);
            float ra[8] = {a0.x, a0.y, a0.z, a0.w, a1.x, a1.y, a1.z, a1.w};
            float rb[8] = {b0.x, b0.y, b0.z, b0.w, b1v.x, b1v.y, b1v.z, b1v.w};
#pragma unroll
            for (int i = 0; i < 8; i++)
#pragma unroll
                for (int j = 0; j < 8; j++)
                    acc[i][j] = fmaf(ra[i], rb[j], acc[i][j]);
        }
        __syncthreads();
    }
#pragma unroll
    for (int i = 0; i < 8; i++) {
        int slot = row0 + ty * 8 + i;
        if (slot < cnt) {
#pragma unroll
            for (int j = 0; j < 8; j++) {
                int c = col0 + tx * 8 + j;
                Ch[(long long)slot * FFd + c] = fmaxf(acc[i][j] + bz[c], 0.f);
            }
        }
    }
}

// ---------------- MoE GEMM2: ybuf = w * (h @ W2[e] + b2[e]) ----------------
__global__ __launch_bounds__(256) void moe_gemm2_kernel(
    const float* __restrict__ W2, const float* __restrict__ b2)
{
    int e = blockIdx.z;
    int cnt = g_counts[e];
    int row0 = blockIdx.y * 128;
    if (row0 >= cnt) return;
    int col0 = blockIdx.x * 128;
    const float* A  = g_h + (long long)e * MAXTOK * FFd;  // [slots, 2048]
    const float* Bm = W2 + (long long)e * FFd * Dm;       // [2048, 512]
    const float* bz = b2 + (long long)e * Dm;

    __shared__ float As[8][128];
    __shared__ float Bs[8][132];

    int tid = threadIdx.x;
    int tx = tid & 15, ty = tid >> 4;
    int aRow = tid >> 1, aK4 = (tid & 1) * 4;
    int bK = tid >> 5, bN4 = (tid & 31) * 4;
    const float* Aptr = A + (long long)(row0 + aRow) * FFd + aK4;
    const float* Bptr = Bm + (long long)bK * Dm + col0 + bN4;

    float acc[8][8];
#pragma unroll
    for (int i = 0; i < 8; i++)
#pragma unroll
        for (int j = 0; j < 8; j++) acc[i][j] = 0.f;

    for (int k0 = 0; k0 < FFd; k0 += 8) {
        float4 a4 = *reinterpret_cast<const float4*>(Aptr + k0);
        float4 b4 = *reinterpret_cast<const float4*>(Bptr + (long long)k0 * Dm);
        As[aK4 + 0][aRow] = a4.x; As[aK4 + 1][aRow] = a4.y;
        As[aK4 + 2][aRow] = a4.z; As[aK4 + 3][aRow] = a4.w;
        *reinterpret_cast<float4*>(&Bs[bK][bN4]) = b4;
        __syncthreads();
#pragma unroll
        for (int k = 0; k < 8; k++) {
            float4 a0 = *reinterpret_cast<const float4*>(&As[k][ty * 8]);
            float4 a1 = *reinterpret_cast<const float4*>(&As[k][ty * 8 + 4]);
            float4 b0 = *reinterpret_cast<const float4*>(&Bs[k][tx * 8]);
            float4 b1v = *reinterpret_cast<const float4*>(&Bs[k][tx * 8 + 4]);
            float ra[8] = {a0.x, a0.y, a0.z, a0.w, a1.x, a1.y, a1.z, a1.w};
            float rb[8] = {b0.x, b0.y, b0.z, b0.w, b1v.x, b1v.y, b1v.z, b1v.w};
#pragma unroll
            for (int i = 0; i < 8; i++)
#pragma unroll
                for (int j = 0; j < 8; j++)
                    acc[i][j] = fmaf(ra[i], rb[j], acc[i][j]);
        }
        __syncthreads();
    }
#pragma unroll
    for (int i = 0; i < 8; i++) {
        int slot = row0 + ty * 8 + i;
        if (slot < cnt) {
            float w = g_wslot[e * MAXTOK + slot];
#pragma unroll
            for (int j = 0; j < 8; j++) {
                int c = col0 + tx * 8 + j;
                g_ybuf[((long long)e * MAXTOK + slot) * Dm + c] = w * (acc[i][j] + bz[c]);
            }
        }
    }
}

// ---------------- combine + LN2 -> out ----------------
__global__ __launch_bounds__(256) void combine_ln2_kernel(
    const float* __restrict__ g, const float* __restrict__ b, float* __restrict__ out)
{
    int t = blockIdx.x, tid = threadIdx.x;
    int s0 = g_slottok[2 * t], s1 = g_slottok[2 * t + 1];
    const float* xr = g_x1 + (long long)t * Dm;
    const float* y0 = g_ybuf + (long long)s0 * Dm;
    const float* y1 = g_ybuf + (long long)s1 * Dm;
    float v0 = xr[tid] + y0[tid] + y1[tid];
    float v1 = xr[tid + 256] + y0[tid + 256] + y1[tid + 256];
    __shared__ float red[256];
    red[tid] = v0 + v1;
    __syncthreads();
    for (int off = 128; off; off >>= 1) { if (tid < off) red[tid] += red[tid + off]; __syncthreads(); }
    float mu = red[0] * (1.0f / 512.0f);
    __syncthreads();
    float d0 = v0 - mu, d1 = v1 - mu;
    red[tid] = d0 * d0 + d1 * d1;
    __syncthreads();
    for (int off = 128; off; off >>= 1) { if (tid < off) red[tid] += red[tid + off]; __syncthreads(); }
    float inv = rsqrtf(red[0] * (1.0f / 512.0f) + 1e-5f);
    out[(long long)t * Dm + tid]       = d0 * inv * g[tid] + b[tid];
    out[(long long)t * Dm + tid + 256] = d1 * inv * g[tid + 256] + b[tid + 256];
}

// ---------------- launch ----------------
extern "C" void kernel_launch(void* const* d_in, const int* in_sizes, int n_in,
                              void* d_out, int out_size)
{
    const float* x    = (const float*)d_in[0];
    const float* fb   = (const float*)d_in[1];
    const float* Wk   = (const float*)d_in[2];
    const float* bk   = (const float*)d_in[3];
    const float* Wv   = (const float*)d_in[4];
    const float* bv   = (const float*)d_in[5];
    const float* Wo   = (const float*)d_in[6];
    const float* bo   = (const float*)d_in[7];
    const float* ln1g = (const float*)d_in[8];
    const float* ln1b = (const float*)d_in[9];
    const float* Wg   = (const float*)d_in[10];
    const float* bg   = (const float*)d_in[11];
    const float* W1   = (const float*)d_in[12];
    const float* b1   = (const float*)d_in[13];
    const float* W2   = (const float*)d_in[14];
    const float* b2   = (const float*)d_in[15];
    const float* ln2g = (const float*)d_in[16];
    const float* ln2b = (const float*)d_in[17];
    float* out = (float*)d_out;

    float *pK, *pV, *pwv, *ptmp, *pkvs;
    cudaGetSymbolAddress((void**)&pK,   g_K);
    cudaGetSymbolAddress((void**)&pV,   g_V);
    cudaGetSymbolAddress((void**)&pwv,  g_wv);
    cudaGetSymbolAddress((void**)&ptmp, g_tmp);
    cudaGetSymbolAddress((void**)&pkvs, g_kvsum);

    dim3 blk(256);

    zero_counts_kernel<<<1, 32>>>();

    // K = x @ Wk + bk ; V = x @ Wv + bv
    gemm_bias_kernel<<<dim3(Dm / 128, BT / 128, 1), blk>>>(
        x, Wk, bk, pK, BT, Dm, Dm, 0, 0, 0, 0);
    gemm_bias_kernel<<<dim3(Dm / 128, BT / 128, 1), blk>>>(
        x, Wv, bv, pV, BT, Dm, Dm, 0, 0, 0, 0);

    // kv_sum[b,d] = sum_t K*V (deterministic two-stage)
    kvsum_partial_kernel<<<dim3(NCHUNK, Bb), 512>>>();
    kvsum_reduce_kernel<<<8, 256>>>();

    // wv[b] = fb[b] @ V[b] + kv_sum[b]  (batched over b)
    gemm_bias_kernel<<<dim3(Dm / 128, Tt / 128, Bb), blk>>>(
        fb, pV, pkvs, pwv, Tt, Dm, Tt,
        (long long)Tt * Tt, (long long)Tt * Dm, (long long)Tt * Dm, Dm);

    // tmp = wv @ Wo + bo
    gemm_bias_kernel<<<dim3(Dm / 128, BT / 128, 1), blk>>>(
        pwv, Wo, bo, ptmp, BT, Dm, Dm, 0, 0, 0, 0);

    // x1 = LN(x + tmp)
    add_ln1_kernel<<<BT, 256>>>(x, ln1g, ln1b);

    // gate + expert routing
    gate_kernel<<<BT, 128>>>(Wg, bg);

    // MoE expert GEMMs (top-2 routed)
    moe_gemm1_kernel<<<dim3(FFd / 128, MAXTOK / 128, Ee), blk>>>(W1, b1);
    moe_gemm2_kernel<<<dim3(Dm / 128, MAXTOK / 128, Ee), blk>>>(W2, b2);

    // out = LN(x1 + ff)
    combine_ln2_kernel<<<BT, 256>>>(ln2g, ln2b, out);
}

// round 2
// speedup vs baseline: 1.0002x; 1.0002x over previous
#include <cuda_runtime.h>
#include <math.h>

// Problem constants
#define Dm 512
#define Tt 2048
#define Bb 4
#define BT 8192          // Bb*Tt
#define FFd 2048
#define Ee 4
#define MAXTOK 8192
#define NCHUNK 16

// ---------------- scratch (device globals: allocation-free) ----------------
__device__ float g_K[BT * Dm];
__device__ float g_V[BT * Dm];
__device__ float g_wv[BT * Dm];
__device__ float g_tmp[BT * Dm];
__device__ float g_x1[BT * Dm];
__device__ float g_part[Bb * NCHUNK * Dm];
__device__ float g_kvsum[Bb * Dm];
__device__ int   g_counts[Ee];
__device__ int   g_tok[Ee * MAXTOK];
__device__ float g_wslot[Ee * MAXTOK];
__device__ int   g_slottok[BT * 2];
__device__ float g_h[(size_t)Ee * MAXTOK * FFd];     // 256 MB
__device__ float g_ybuf[(size_t)Ee * MAXTOK * Dm];   // 64 MB

// ---------------- misc small kernels ----------------
__global__ void zero_counts_kernel() {
    if (threadIdx.x < Ee) g_counts[threadIdx.x] = 0;
}

// kv_sum partials: grid(NCHUNK, Bb), block 512
__global__ void kvsum_partial_kernel() {
    int b = blockIdx.y, tc = blockIdx.x, d = threadIdx.x;
    const float* Kp = g_K + ((long long)b * Tt + (long long)tc * (Tt / NCHUNK)) * Dm;
    const float* Vp = g_V + ((long long)b * Tt + (long long)tc * (Tt / NCHUNK)) * Dm;
    float s = 0.f;
    for (int t = 0; t < Tt / NCHUNK; ++t)
        s += Kp[(long long)t * Dm + d] * Vp[(long long)t * Dm + d];
    g_part[((long long)b * NCHUNK + tc) * Dm + d] = s;
}

// reduce partials: grid 8, block 256  (Bb*Dm = 2048 outputs)
__global__ void kvsum_reduce_kernel() {
    int i = blockIdx.x * 256 + threadIdx.x;  // i = b*Dm + d
    int b = i >> 9, d = i & 511;
    float s = 0.f;
    for (int tc = 0; tc < NCHUNK; ++tc)
        s += g_part[((long long)b * NCHUNK + tc) * Dm + d];
    g_kvsum[i] = s;
}

// ---------------- generic tiled GEMM: C[z] = A[z] @ B[z] + bias[z] ----------------
// BM=BN=128, BK=8, 256 threads, 8x8 microtile. Requires M%128==0, N%128==0, K%8==0.
__global__ __launch_bounds__(256) void gemm_bias_kernel(
    const float* __restrict__ A, const float* __restrict__ Bm,
    const float* __restrict__ bias, float* __restrict__ C,
    int M, int N, int K,
    long long sA, long long sB, long long sC, long long sBias)
{
    int z = blockIdx.z;
    A  += (long long)z * sA;
    Bm += (long long)z * sB;
    C  += (long long)z * sC;
    const float* bz = bias + (long long)z * sBias;

    __shared__ float As[8][128];
    __shared__ float Bs[8][132];

    int tid = threadIdx.x;
    int tx = tid & 15, ty = tid >> 4;
    int row0 = blockIdx.y * 128, col0 = blockIdx.x * 128;
    int aRow = tid >> 1, aK4 = (tid & 1) * 4;
    int bK = tid >> 5, bN4 = (tid & 31) * 4;

    const float* Aptr = A + (long long)(row0 + aRow) * K + aK4;
    const float* Bptr = Bm + (long long)bK * N + col0 + bN4;

    float acc[8][8];
#pragma unroll
    for (int i = 0; i < 8; i++)
#pragma unroll
        for (int j = 0; j < 8; j++) acc[i][j] = 0.f;

    for (int k0 = 0; k0 < K; k0 += 8) {
        float4 a4 = *reinterpret_cast<const float4*>(Aptr + k0);
        float4 b4 = *reinterpret_cast<const float4*>(Bptr + (long long)k0 * N);
        As[aK4 + 0][aRow] = a4.x; As[aK4 + 1][aRow] = a4.y;
        As[aK4 + 2][aRow] = a4.z; As[aK4 + 3][aRow] = a4.w;
        *reinterpret_cast<float4*>(&Bs[bK][bN4]) = b4;
        __syncthreads();
#pragma unroll
        for (int k = 0; k < 8; k++) {
            float4 a0 = *reinterpret_cast<const float4*>(&As[k][ty * 8]);
            float4 a1 = *reinterpret_cast<const float4*>(&As[k][ty * 8 + 4]);
            float4 b0 = *reinterpret_cast<const float4*>(&Bs[k][tx * 8]);
            float4 b1 = *reinterpret_cast<const float4*>(&Bs[k][tx * 8 + 4]);
            float ra[8] = {a0.x, a0.y, a0.z, a0.w, a1.x, a1.y, a1.z, a1.w};
            float rb[8] = {b0.x, b0.y, b0.z, b0.w, b1.x, b1.y, b1.z, b1.w};
#pragma unroll
            for (int i = 0; i < 8; i++)
#pragma unroll
                for (int j = 0; j < 8; j++)
                    acc[i][j] = fmaf(ra[i], rb[j], acc[i][j]);
        }
        __syncthreads();
    }
#pragma unroll
    for (int i = 0; i < 8; i++) {
        long long r = row0 + ty * 8 + i;
#pragma unroll
        for (int j = 0; j < 8; j++) {
            int c = col0 + tx * 8 + j;
            C[r * N + c] = acc[i][j] + bz[c];
        }
    }
}

// ---------------- LN1: x1 = LN(x + tmp) ----------------
__global__ __launch_bounds__(256) void add_ln1_kernel(
    const float* __restrict__ x, const float* __restrict__ g, const float* __restrict__ b)
{
    int t = blockIdx.x, tid = threadIdx.x;
    const float* xr = x + (long long)t * Dm;
    const float* tr = g_tmp + (long long)t * Dm;
    float v0 = xr[tid] + tr[tid];
    float v1 = xr[tid + 256] + tr[tid + 256];
    __shared__ float red[256];
    red[tid] = v0 + v1;
    __syncthreads();
    for (int off = 128; off; off >>= 1) { if (tid < off) red[tid] += red[tid + off]; __syncthreads(); }
    float mu = red[0] * (1.0f / 512.0f);
    __syncthreads();
    float d0 = v0 - mu, d1 = v1 - mu;
    red[tid] = d0 * d0 + d1 * d1;
    __syncthreads();
    for (int off = 128; off; off >>= 1) { if (tid < off) red[tid] += red[tid + off]; __syncthreads(); }
    float inv = rsqrtf(red[0] * (1.0f / 512.0f) + 1e-5f);
    g_x1[(long long)t * Dm + tid]       = d0 * inv * g[tid] + b[tid];
    g_x1[(long long)t * Dm + tid + 256] = d1 * inv * g[tid + 256] + b[tid + 256];
}

// ---------------- gate: softmax(x1@Wg+bg), top-2, build expert slot lists ----------------
__global__ __launch_bounds__(128) void gate_kernel(
    const float* __restrict__ Wg, const float* __restrict__ bg)
{
    int t = blockIdx.x, tid = threadIdx.x;
    const float* xr = g_x1 + (long long)t * Dm;
    float p0 = 0, p1 = 0, p2 = 0, p3 = 0;
    const float4* Wg4 = reinterpret_cast<const float4*>(Wg);
    for (int d = tid; d < Dm; d += 128) {
        float xv = xr[d];
        float4 w = Wg4[d];
        p0 = fmaf(xv, w.x, p0); p1 = fmaf(xv, w.y, p1);
        p2 = fmaf(xv, w.z, p2); p3 = fmaf(xv, w.w, p3);
    }
    __shared__ float sm[4][128];
    sm[0][tid] = p0; sm[1][tid] = p1; sm[2][tid] = p2; sm[3][tid] = p3;
    __syncthreads();
    for (int off = 64; off; off >>= 1) {
        if (tid < off) {
            sm[0][tid] += sm[0][tid + off];
            sm[1][tid] += sm[1][tid + off];
            sm[2][tid] += sm[2][tid + off];
            sm[3][tid] += sm[3][tid + off];
        }
        __syncthreads();
    }
    if (tid == 0) {
        float s[4] = { sm[0][0] + bg[0], sm[1][0] + bg[1], sm[2][0] + bg[2], sm[3][0] + bg[3] };
        float m = fmaxf(fmaxf(s[0], s[1]), fmaxf(s[2], s[3]));
        float ex[4]; float sum = 0.f;
        for (int e = 0; e < 4; e++) { ex[e] = expf(s[e] - m); sum += ex[e]; }
        float invs = 1.0f / sum;
        float pr[4];
        for (int e = 0; e < 4; e++) pr[e] = ex[e] * invs;
        int i0 = 0;
        for (int e = 1; e < 4; e++) if (pr[e] > pr[i0]) i0 = e;
        int i1 = -1;
        for (int e = 0; e < 4; e++) {
            if (e == i0) continue;
            if (i1 < 0 || pr[e] > pr[i1]) i1 = e;
        }
        int s0 = atomicAdd(&g_counts[i0], 1);
        g_tok[i0 * MAXTOK + s0] = t;
        g_wslot[i0 * MAXTOK + s0] = pr[i0];
        g_slottok[2 * t] = i0 * MAXTOK + s0;
        int s1 = atomicAdd(&g_counts[i1], 1);
        g_tok[i1 * MAXTOK + s1] = t;
        g_wslot[i1 * MAXTOK + s1] = pr[i1];
        g_slottok[2 * t + 1] = i1 * MAXTOK + s1;
    }
}

// ---------------- MoE GEMM1 (gather): h = relu(x1[tok] @ W1[e] + b1[e]) ----------------
__global__ __launch_bounds__(256) void moe_gemm1_kernel(
    const float* __restrict__ W1, const float* __restrict__ b1)
{
    int e = blockIdx.z;
    int cnt = g_counts[e];
    int row0 = blockIdx.y * 128;
    if (row0 >= cnt) return;
    int col0 = blockIdx.x * 128;
    const float* Bm = W1 + (long long)e * Dm * FFd;   // [512, 2048]
    const float* bz = b1 + (long long)e * FFd;
    float* Ch = g_h + (long long)e * MAXTOK * FFd;

    __shared__ int toks[128];
    __shared__ float As[8][128];
    __shared__ float Bs[8][132];

    int tid = threadIdx.x;
    if (tid < 128) {
        int slot = row0 + tid;
        toks[tid] = (slot < cnt) ? g_tok[e * MAXTOK + slot] : 0;
    }
    __syncthreads();
    int tx = tid & 15, ty = tid >> 4;
    int aRow = tid >> 1, aK4 = (tid & 1) * 4;
    int bK = tid >> 5, bN4 = (tid & 31) * 4;
    const float* Aptr = g_x1 + (long long)toks[aRow] * Dm + aK4;
    const float* Bptr = Bm + (long long)bK * FFd + col0 + bN4;

    float acc[8][8];
#pragma unroll
    for (int i = 0; i < 8; i++)
#pragma unroll
        for (int j = 0; j < 8; j++) acc[i][j] = 0.f;

    for (int k0 = 0; k0 < Dm; k0 += 8) {
        float4 a4 = *reinterpret_cast<const float4*>(Aptr + k0);
        float4 b4 = *reinterpret_cast<const float4*>(Bptr + (long long)k0 * FFd);
        As[aK4 + 0][aRow] = a4.x; As[aK4 + 1][aRow] = a4.y;
        As[aK4 + 2][aRow] = a4.z; As[aK4 + 3][aRow] = a4.w;
        *reinterpret_cast<float4*>(&Bs[bK][bN4]) = b4;
        __syncthreads();
#pragma unroll
        for (int k = 0; k < 8; k++) {
            float4 a0 = *reinterpret_cast<const float4*>(&As[k][ty * 8]);
            float4 a1 = *reinterpret_cast<const float4*>(&As[k][ty * 8 + 4]);
            float4 b0 = *reinterpret_cast<const float4*>(&Bs[k][tx * 8]);
            float4 b1v = *reinterpret_cast<const float4*>(&Bs[k][tx * 8 + 4]);
            float ra[8] = {a0.x, a0.y, a0.z, a0.w, a1.x, a1.y, a1.z, a1.w};
            float rb[8] = {b0.x, b0.y, b0.z, b0.w, b1v.x, b1v.y, b1v.z, b1v.w};
#pragma unroll
            for (int i = 0; i < 8; i++)
#pragma unroll
                for (int j = 0; j < 8; j++)
                    acc[i][j] = fmaf(ra[i], rb[j], acc[i][j]);
        }
        __syncthreads();
    }
#pragma unroll
    for (int i = 0; i < 8; i++) {
        int slot = row0 + ty * 8 + i;
        if (slot < cnt) {
#pragma unroll
            for (int j = 0; j < 8; j++) {
                int c = col0 + tx * 8 + j;
                Ch[(long long)slot * FFd + c] = fmaxf(acc[i][j] + bz[c], 0.f);
            }
        }
    }
}

// ---------------- MoE GEMM2: ybuf = w * (h @ W2[e] + b2[e]) ----------------
__global__ __launch_bounds__(256) void moe_gemm2_kernel(
    const float* __restrict__ W2, const float* __restrict__ b2)
{
    int e = blockIdx.z;
    int cnt = g_counts[e];
    int row0 = blockIdx.y * 128;
    if (row0 >= cnt) return;
    int col0 = blockIdx.x * 128;
    const float* A  = g_h + (long long)e * MAXTOK * FFd;  // [slots, 2048]
    const float* Bm = W2 + (long long)e * FFd * Dm;       // [2048, 512]
    const float* bz = b2 + (long long)e * Dm;

    __shared__ float As[8][128];
    __shared__ float Bs[8][132];

    int tid = threadIdx.x;
    int tx = tid & 15, ty = tid >> 4;
    int aRow = tid >> 1, aK4 = (tid & 1) * 4;
    int bK = tid >> 5, bN4 = (tid & 31) * 4;
    const float* Aptr = A + (long long)(row0 + aRow) * FFd + aK4;
    const float* Bptr = Bm + (long long)bK * Dm + col0 + bN4;

    float acc[8][8];
#pragma unroll
    for (int i = 0; i < 8; i++)
#pragma unroll
        for (int j = 0; j < 8; j++) acc[i][j] = 0.f;

    for (int k0 = 0; k0 < FFd; k0 += 8) {
        float4 a4 = *reinterpret_cast<const float4*>(Aptr + k0);
        float4 b4 = *reinterpret_cast<const float4*>(Bptr + (long long)k0 * Dm);
        As[aK4 + 0][aRow] = a4.x; As[aK4 + 1][aRow] = a4.y;
        As[aK4 + 2][aRow] = a4.z; As[aK4 + 3][aRow] = a4.w;
        *reinterpret_cast<float4*>(&Bs[bK][bN4]) = b4;
        __syncthreads();
#pragma unroll
        for (int k = 0; k < 8; k++) {
            float4 a0 = *reinterpret_cast<const float4*>(&As[k][ty * 8]);
            float4 a1 = *reinterpret_cast<const float4*>(&As[k][ty * 8 + 4]);
            float4 b0 = *reinterpret_cast<const float4*>(&Bs[k][tx * 8]);
            float4 b1v = *reinterpret_cast<const float4*>(&Bs[k][tx * 8 + 4]);
            float ra[8] = {a0.x, a0.y, a0.z, a0.w, a1.x, a1.y, a1.z, a1.w};
            float rb[8] = {b0.x, b0.y, b0.z, b0.w, b1v.x, b1v.y, b1v.z, b1v.w};
#pragma unroll
            for (int i = 0; i < 8; i++)
#pragma unroll
                for (int j = 0; j < 8; j++)
                    acc[i][j] = fmaf(ra[i], rb[j], acc[i][j]);
        }
        __syncthreads();
    }
#pragma unroll
    for (int i = 0; i < 8; i++) {
        int slot = row0 + ty * 8 + i;
        if (slot < cnt) {
            float w = g_wslot[e * MAXTOK + slot];
#pragma unroll
            for (int j = 0; j < 8; j++) {
                int c = col0 + tx * 8 + j;
                g_ybuf[((long long)e * MAXTOK + slot) * Dm + c] = w * (acc[i][j] + bz[c]);
            }
        }
    }
}

// ---------------- combine + LN2 -> out ----------------
__global__ __launch_bounds__(256) void combine_ln2_kernel(
    const float* __restrict__ g, const float* __restrict__ b, float* __restrict__ out)
{
    int t = blockIdx.x, tid = threadIdx.x;
    int s0 = g_slottok[2 * t], s1 = g_slottok[2 * t + 1];
    const float* xr = g_x1 + (long long)t * Dm;
    const float* y0 = g_ybuf + (long long)s0 * Dm;
    const float* y1 = g_ybuf + (long long)s1 * Dm;
    float v0 = xr[tid] + y0[tid] + y1[tid];
    float v1 = xr[tid + 256] + y0[tid + 256] + y1[tid + 256];
    __shared__ float red[256];
    red[tid] = v0 + v1;
    __syncthreads();
    for (int off = 128; off; off >>= 1) { if (tid < off) red[tid] += red[tid + off]; __syncthreads(); }
    float mu = red[0] * (1.0f / 512.0f);
    __syncthreads();
    float d0 = v0 - mu, d1 = v1 - mu;
    red[tid] = d0 * d0 + d1 * d1;
    __syncthreads();
    for (int off = 128; off; off >>= 1) { if (tid < off) red[tid] += red[tid + off]; __syncthreads(); }
    float inv = rsqrtf(red[0] * (1.0f / 512.0f) + 1e-5f);
    out[(long long)t * Dm + tid]       = d0 * inv * g[tid] + b[tid];
    out[(long long)t * Dm + tid + 256] = d1 * inv * g[tid + 256] + b[tid + 256];
}

// ---------------- launch ----------------
extern "C" void kernel_launch(void* const* d_in, const int* in_sizes, int n_in,
                              void* d_out, int out_size)
{
    const float* x    = (const float*)d_in[0];
    const float* fb   = (const float*)d_in[1];
    const float* Wk   = (const float*)d_in[2];
    const float* bk   = (const float*)d_in[3];
    const float* Wv   = (const float*)d_in[4];
    const float* bv   = (const float*)d_in[5];
    const float* Wo   = (const float*)d_in[6];
    const float* bo   = (const float*)d_in[7];
    const float* ln1g = (const float*)d_in[8];
    const float* ln1b = (const float*)d_in[9];
    const float* Wg   = (const float*)d_in[10];
    const float* bg   = (const float*)d_in[11];
    const float* W1   = (const float*)d_in[12];
    const float* b1   = (const float*)d_in[13];
    const float* W2   = (const float*)d_in[14];
    const float* b2   = (const float*)d_in[15];
    const float* ln2g = (const float*)d_in[16];
    const float* ln2b = (const float*)d_in[17];
    float* out = (float*)d_out;

    float *pK, *pV, *pwv, *ptmp, *pkvs;
    cudaGetSymbolAddress((void**)&pK,   g_K);
    cudaGetSymbolAddress((void**)&pV,   g_V);
    cudaGetSymbolAddress((void**)&pwv,  g_wv);
    cudaGetSymbolAddress((void**)&ptmp, g_tmp);
    cudaGetSymbolAddress((void**)&pkvs, g_kvsum);

    dim3 blk(256);

    zero_counts_kernel<<<1, 32>>>();

    // K = x @ Wk + bk ; V = x @ Wv + bv
    gemm_bias_kernel<<<dim3(Dm / 128, BT / 128, 1), blk>>>(
        x, Wk, bk, pK, BT, Dm, Dm, 0, 0, 0, 0);
    gemm_bias_kernel<<<dim3(Dm / 128, BT / 128, 1), blk>>>(
        x, Wv, bv, pV, BT, Dm, Dm, 0, 0, 0, 0);

    // kv_sum[b,d] = sum_t K*V (deterministic two-stage)
    kvsum_partial_kernel<<<dim3(NCHUNK, Bb), 512>>>();
    kvsum_reduce_kernel<<<8, 256>>>();

    // wv[b] = fb[b] @ V[b] + kv_sum[b]  (batched over b)
    gemm_bias_kernel<<<dim3(Dm / 128, Tt / 128, Bb), blk>>>(
        fb, pV, pkvs, pwv, Tt, Dm, Tt,
        (long long)Tt * Tt, (long long)Tt * Dm, (long long)Tt * Dm, Dm);

    // tmp = wv @ Wo + bo
    gemm_bias_kernel<<<dim3(Dm / 128, BT / 128, 1), blk>>>(
        pwv, Wo, bo, ptmp, BT, Dm, Dm, 0, 0, 0, 0);

    // x1 = LN(x + tmp)
    add_ln1_kernel<<<BT, 256>>>(x, ln1g, ln1b);

    // gate + expert routing
    gate_kernel<<<BT, 128>>>(Wg, bg);

    // MoE expert GEMMs (top-2 routed)
    moe_gemm1_kernel<<<dim3(FFd / 128, MAXTOK / 128, Ee), blk>>>(W1, b1);
    moe_gemm2_kernel<<<dim3(Dm / 128, MAXTOK / 128, Ee), blk>>>(W2, b2);

    // out = LN(x1 + ff)
    combine_ln2_kernel<<<BT, 256>>>(ln2g, ln2b, out);
}